// round 1
// baseline (speedup 1.0000x reference)
#include <cuda_runtime.h>

#define BATCH 4
#define C_LIDAR 128
#define HGT 256
#define WID 256
#define HW (HGT*WID)
#define C_CAM 256
#define HEADS 4
#define DIM_HEAD 32
#define HD 128
#define N_TOK 8192
#define TB 8
#define SCALE 0.17677669529663687f  /* 1/sqrt(32) */

// scratch (static __device__ allocation is allowed)
__device__ float g_v[(size_t)BATCH * N_TOK * HD];        // 16.8 MB
__device__ float g_s[(size_t)BATCH * HEADS * N_TOK];     // logits
__device__ float g_red[BATCH * HEADS * 2];               // (max, 1/sumexp)

// ---------------------------------------------------------------------------
// Kernel 1: out = lidar + alpha * out_bias[c]   (dense, float4)
// ---------------------------------------------------------------------------
__global__ void bias_copy_kernel(const float* __restrict__ lidar,
                                 const float* __restrict__ out_bias,
                                 const float* __restrict__ alpha_p,
                                 float* __restrict__ out) {
    int i4 = blockIdx.x * blockDim.x + threadIdx.x;   // float4 index
    int c = (i4 >> 14) & 127;                         // (i4*4 / 65536) % 128
    float alpha = __ldg(alpha_p);
    float bb = alpha * __ldg(&out_bias[c]);
    float4 v = ((const float4*)lidar)[i4];
    v.x += bb; v.y += bb; v.z += bb; v.w += bb;
    ((float4*)out)[i4] = v;
}

// ---------------------------------------------------------------------------
// Kernel 2: per-token k, v, q-gather, logit.  Block = 128 threads, TB tokens.
// Thread tid owns output channel hd = tid for k/v/q. Warp w == head w.
// ---------------------------------------------------------------------------
__global__ __launch_bounds__(128) void token_fwd_kernel(
    const float* __restrict__ lidar, const float* __restrict__ tok,
    const int* __restrict__ idx, const float* __restrict__ q_w,
    const float* __restrict__ q_bias, const float* __restrict__ k_w,
    const float* __restrict__ v_w) {
    __shared__ __align__(16) float s_tok[TB][C_CAM];
    __shared__ __align__(16) float s_x[TB][C_LIDAR];

    int b = blockIdx.y;
    int t0 = blockIdx.x * TB;
    int tid = threadIdx.x;

    // load TB token feature rows (fully coalesced, float4)
    const float4* tok4 = (const float4*)(tok + ((size_t)b * N_TOK + t0) * C_CAM);
    float4* stok4 = (float4*)&s_tok[0][0];
#pragma unroll
    for (int p = 0; p < (TB * C_CAM / 4) / 128; p++) {
        int f = p * 128 + tid;
        stok4[f] = tok4[f];
    }
    // gather lidar feature vectors at token positions (scattered, 1 sector/elem)
#pragma unroll
    for (int j = 0; j < TB; j++) {
        int ii = idx[((size_t)b * N_TOK + t0 + j) * 2 + 0];
        int jj = idx[((size_t)b * N_TOK + t0 + j) * 2 + 1];
        ii = min(max(ii, 0), HGT - 1);
        jj = min(max(jj, 0), WID - 1);
        s_x[j][tid] = __ldg(&lidar[(((size_t)b * C_LIDAR + tid) * HGT + ii) * WID + jj]);
    }
    __syncthreads();

    int hd = tid;
    float acc_k[TB], acc_v[TB], acc_q[TB];
#pragma unroll
    for (int j = 0; j < TB; j++) { acc_k[j] = 0.f; acc_v[j] = 0.f; acc_q[j] = 0.f; }

    // k, v: 256-dim dots; weight float4 loaded once, reused across TB tokens
    const float4* kw4 = (const float4*)(k_w + (size_t)hd * C_CAM);
    const float4* vw4 = (const float4*)(v_w + (size_t)hd * C_CAM);
#pragma unroll 4
    for (int i4 = 0; i4 < C_CAM / 4; i4++) {
        float4 wk = kw4[i4];
        float4 wv = vw4[i4];
#pragma unroll
        for (int j = 0; j < TB; j++) {
            float4 t = ((const float4*)s_tok[j])[i4];
            acc_k[j] += wk.x * t.x + wk.y * t.y + wk.z * t.z + wk.w * t.w;
            acc_v[j] += wv.x * t.x + wv.y * t.y + wv.z * t.z + wv.w * t.w;
        }
    }
    // q: 128-dim dots on gathered lidar features
    const float4* qw4 = (const float4*)(q_w + (size_t)hd * C_LIDAR);
#pragma unroll 4
    for (int i4 = 0; i4 < C_LIDAR / 4; i4++) {
        float4 wq = qw4[i4];
#pragma unroll
        for (int j = 0; j < TB; j++) {
            float4 x = ((const float4*)s_x[j])[i4];
            acc_q[j] += wq.x * x.x + wq.y * x.y + wq.z * x.z + wq.w * x.w;
        }
    }

    float qb = __ldg(&q_bias[hd]);
    int h = tid >> 5;  // warp id == head id
#pragma unroll
    for (int j = 0; j < TB; j++) {
        float p = (acc_q[j] + qb) * acc_k[j];
#pragma unroll
        for (int off = 16; off > 0; off >>= 1)
            p += __shfl_down_sync(0xffffffffu, p, off);
        if ((tid & 31) == 0)
            g_s[((size_t)b * HEADS + h) * N_TOK + t0 + j] = p * SCALE;
        // store v (coalesced)
        g_v[((size_t)(b * N_TOK + t0 + j)) * HD + hd] = acc_v[j];
    }
}

// ---------------------------------------------------------------------------
// Kernel 3: per (b,h): max + sum(exp) over 8192 logits
// ---------------------------------------------------------------------------
__global__ void softmax_reduce_kernel() {
    int bh = blockIdx.x;  // 0..15
    const float* s = g_s + (size_t)bh * N_TOK;
    __shared__ float red[256];
    int tid = threadIdx.x;

    float m = -1e30f;
    for (int i = tid; i < N_TOK; i += 256) m = fmaxf(m, s[i]);
    red[tid] = m;
    __syncthreads();
#pragma unroll
    for (int st = 128; st > 0; st >>= 1) {
        if (tid < st) red[tid] = fmaxf(red[tid], red[tid + st]);
        __syncthreads();
    }
    m = red[0];
    __syncthreads();

    float sum = 0.f;
    for (int i = tid; i < N_TOK; i += 256) sum += expf(s[i] - m);
    red[tid] = sum;
    __syncthreads();
#pragma unroll
    for (int st = 128; st > 0; st >>= 1) {
        if (tid < st) red[tid] += red[tid + st];
        __syncthreads();
    }
    if (tid == 0) {
        g_red[bh * 2 + 0] = m;
        g_red[bh * 2 + 1] = 1.0f / red[0];
    }
}

// ---------------------------------------------------------------------------
// Kernel 4: a = softmax*gate; fused = a*v; out-proj; atomic scatter into out.
// ---------------------------------------------------------------------------
__global__ __launch_bounds__(128) void scatter_kernel(
    const int* __restrict__ idx, const float* __restrict__ gate,
    const float* __restrict__ alpha_p, const float* __restrict__ out_w,
    float* __restrict__ out) {
    __shared__ __align__(16) float s_f[TB][HD];
    __shared__ float s_a[TB][HEADS];
    __shared__ int s_ij[TB];

    int b = blockIdx.y;
    int t0 = blockIdx.x * TB;
    int tid = threadIdx.x;
    float alpha = __ldg(alpha_p);

    if (tid < TB * HEADS) {
        int j = tid / HEADS, h = tid % HEADS;
        int bh = b * HEADS + h;
        float m = g_red[bh * 2 + 0];
        float inv = g_red[bh * 2 + 1];
        float sv = g_s[(size_t)bh * N_TOK + t0 + j];
        s_a[j][h] = expf(sv - m) * inv * __ldg(&gate[(size_t)b * N_TOK + t0 + j]);
    }
    if (tid < TB) {
        int ii = idx[((size_t)b * N_TOK + t0 + tid) * 2 + 0];
        int jj = idx[((size_t)b * N_TOK + t0 + tid) * 2 + 1];
        ii = min(max(ii, 0), HGT - 1);
        jj = min(max(jj, 0), WID - 1);
        s_ij[tid] = ii * WID + jj;
    }
    __syncthreads();

    // fused = a[head]*v
    int hd = tid, h = tid >> 5;
#pragma unroll
    for (int j = 0; j < TB; j++)
        s_f[j][hd] = s_a[j][h] * g_v[((size_t)(b * N_TOK + t0 + j)) * HD + hd];
    __syncthreads();

    // out-projection: thread tid owns output channel c
    int c = tid;
    float acc[TB];
#pragma unroll
    for (int j = 0; j < TB; j++) acc[j] = 0.f;
    const float4* ow4 = (const float4*)(out_w + (size_t)c * HD);
#pragma unroll 4
    for (int i4 = 0; i4 < HD / 4; i4++) {
        float4 w = ow4[i4];
#pragma unroll
        for (int j = 0; j < TB; j++) {
            float4 f = ((const float4*)s_f[j])[i4];
            acc[j] += w.x * f.x + w.y * f.y + w.z * f.z + w.w * f.w;
        }
    }
#pragma unroll
    for (int j = 0; j < TB; j++)
        atomicAdd(&out[((size_t)b * C_LIDAR + c) * HW + s_ij[j]], alpha * acc[j]);
}

// ---------------------------------------------------------------------------
extern "C" void kernel_launch(void* const* d_in, const int* in_sizes, int n_in,
                              void* d_out, int out_size) {
    const float* lidar    = (const float*)d_in[0];
    const float* tok      = (const float*)d_in[1];
    const int*   idx      = (const int*)  d_in[2];
    const float* gate     = (const float*)d_in[3];
    const float* alpha    = (const float*)d_in[4];
    const float* q_w      = (const float*)d_in[5];
    const float* q_bias   = (const float*)d_in[6];
    const float* k_w      = (const float*)d_in[7];
    const float* v_w      = (const float*)d_in[8];
    const float* out_w    = (const float*)d_in[9];
    const float* out_bias = (const float*)d_in[10];
    float* out = (float*)d_out;

    // total float4 = 4*128*256*256/4 = 8,388,608 -> 32768 blocks of 256
    bias_copy_kernel<<<32768, 256>>>(lidar, out_bias, alpha, out);

    dim3 g(N_TOK / TB, BATCH);
    token_fwd_kernel<<<g, 128>>>(lidar, tok, idx, q_w, q_bias, k_w, v_w);
    softmax_reduce_kernel<<<16, 256>>>();
    scatter_kernel<<<g, 128>>>(idx, gate, alpha, out_w, out);
}